// round 4
// baseline (speedup 1.0000x reference)
#include <cuda_runtime.h>
#include <math.h>

#define N_NODES   100000
#define N_EDGES   6400000
#define F_IN      128
#define F_HID     16
#define N_CLASSES 10
#define HPAD      16   // layer-2 rows padded 10 -> 16 floats (64B rows)

// ---- scratch (device globals: no allocation allowed) ----
// NOTE: never pass these as kernel args from host code (host sees the shadow
// symbol, not the device address — that was the R1-R3 bug). All access is
// from device code directly.
__device__ int   g_deg [N_NODES];
__device__ float g_dinv[N_NODES];
__device__ __align__(16) float g_norm[N_EDGES];
__device__ __align__(16) float g_h1  [N_NODES * F_HID];
__device__ __align__(16) float g_agg1[N_NODES * F_HID];
__device__ __align__(16) float g_h2  [N_NODES * HPAD];
__device__ __align__(16) float g_agg2[N_NODES * HPAD];

// pointers resolved on-device (x vs edge_index have identical element counts)
__device__ const float* g_xp;
__device__ const int*   g_eip;

// ---------------------------------------------------------------- probe
// Disambiguate the two 12.8M-element buffers: edge_index values are int32 in
// [0, 100000); x ~ N(0,1) floats have bit patterns >= ~0x3c000000.
__global__ void probe_kernel(const void* a, const void* b) {
    if (threadIdx.x != 0 || blockIdx.x != 0) return;
    const unsigned* ua = (const unsigned*)a;
    bool a_is_int = true;
    for (int i = 0; i < 16; i++)
        if (ua[i] >= 100000u) { a_is_int = false; break; }
    if (a_is_int) { g_eip = (const int*)a; g_xp = (const float*)b; }
    else          { g_eip = (const int*)b; g_xp = (const float*)a; }
}

// ---------------------------------------------------------------- zero
__global__ void zero_kernel() {
    int i = blockIdx.x * blockDim.x + threadIdx.x;
    const int n = N_NODES * F_HID;
    if (i < n) { g_agg1[i] = 0.f; g_agg2[i] = 0.f; }
    if (i < N_NODES) g_deg[i] = 0;
}

// ---------------------------------------------------------------- degree (in-degree over dst)
__global__ void degree_kernel() {
    int e = blockIdx.x * blockDim.x + threadIdx.x;
    const int* dst = g_eip + N_EDGES;
    if (e < N_EDGES) atomicAdd(&g_deg[dst[e]], 1);
}

// ---------------------------------------------------------------- dinv
__global__ void dinv_kernel() {
    int i = blockIdx.x * blockDim.x + threadIdx.x;
    if (i < N_NODES) g_dinv[i] = rsqrtf((float)(g_deg[i] + 1)); // +1 = self-loop
}

// ---------------------------------------------------------------- per-edge norm
__global__ void norm_kernel() {
    int e = blockIdx.x * blockDim.x + threadIdx.x;
    const int* src = g_eip;
    const int* dst = g_eip + N_EDGES;
    if (e < N_EDGES) g_norm[e] = g_dinv[src[e]] * g_dinv[dst[e]];
}

// ---------------------------------------------------------------- h1 = x @ W1
// 128 threads/block; thread = one node row (16 outputs).
__global__ void gemm1_kernel(const float* __restrict__ W1) {
    __shared__ float sW[F_IN * F_HID];
    int tid = threadIdx.x;
    #pragma unroll
    for (int j = 0; j < 16; j++) sW[tid * 16 + j] = W1[tid * 16 + j];
    __syncthreads();

    int row = blockIdx.x * 128 + tid;
    if (row >= N_NODES) return;

    const float4* xr = (const float4*)(g_xp + (size_t)row * F_IN);
    float acc[F_HID];
    #pragma unroll
    for (int f = 0; f < F_HID; f++) acc[f] = 0.f;

    #pragma unroll 4
    for (int k4 = 0; k4 < F_IN / 4; k4++) {
        float4 xv = xr[k4];
        const float* wk = &sW[k4 * 4 * F_HID];
        #pragma unroll
        for (int f = 0; f < F_HID; f++)
            acc[f] += xv.x * wk[f] + xv.y * wk[F_HID + f]
                    + xv.z * wk[2 * F_HID + f] + xv.w * wk[3 * F_HID + f];
    }

    float4* o = (float4*)(g_h1 + (size_t)row * F_HID);
    o[0] = make_float4(acc[0],  acc[1],  acc[2],  acc[3]);
    o[1] = make_float4(acc[4],  acc[5],  acc[6],  acc[7]);
    o[2] = make_float4(acc[8],  acc[9],  acc[10], acc[11]);
    o[3] = make_float4(acc[12], acc[13], acc[14], acc[15]);
}

// ---------------------------------------------------------------- scatter (both layers)
// 4 lanes per edge: lane q handles floats [4q, 4q+4). Globals referenced from
// DEVICE code (template selects layer) — correct device addresses guaranteed.
template<int LAYER>
__global__ void scatter_kernel() {
    unsigned t = blockIdx.x * blockDim.x + threadIdx.x;
    int e = (int)(t >> 2);
    if (e >= N_EDGES) return;
    int q = (int)(t & 3u);

    const float* h  = (LAYER == 1) ? g_h1   : g_h2;
    float*       agg = (LAYER == 1) ? g_agg1 : g_agg2;

    const int* src = g_eip;
    const int* dst = g_eip + N_EDGES;
    int s = src[e];
    int d = dst[e];
    float nm = g_norm[e];

    float4 v = ((const float4*)(h + (size_t)s * 16))[q];
    float4* ap = ((float4*)(agg + (size_t)d * 16)) + q;
    asm volatile("red.global.add.v4.f32 [%0], {%1,%2,%3,%4};"
                 :: "l"(ap), "f"(v.x * nm), "f"(v.y * nm), "f"(v.z * nm), "f"(v.w * nm)
                 : "memory");
}

// ---------------------------------------------------------------- mid: z = relu(agg1 + self + b1); h2 = z @ W2 (padded)
__global__ void mid_kernel(const float* __restrict__ b1, const float* __restrict__ W2) {
    __shared__ float sW2[F_HID * N_CLASSES]; // 160
    __shared__ float sb1[F_HID];
    int tid = threadIdx.x;
    if (tid < F_HID * N_CLASSES) sW2[tid] = W2[tid];
    if (tid < F_HID) sb1[tid] = b1[tid];
    __syncthreads();

    int i = blockIdx.x * blockDim.x + tid;
    if (i >= N_NODES) return;

    float dii = g_dinv[i];
    float sl  = dii * dii; // self-loop norm

    float z[F_HID];
    #pragma unroll
    for (int f = 0; f < F_HID; f++) {
        float v = g_agg1[(size_t)i * F_HID + f] + g_h1[(size_t)i * F_HID + f] * sl + sb1[f];
        z[f] = v > 0.f ? v : 0.f;
    }

    float o[HPAD];
    #pragma unroll
    for (int c = 0; c < N_CLASSES; c++) {
        float s = 0.f;
        #pragma unroll
        for (int f = 0; f < F_HID; f++) s += z[f] * sW2[f * N_CLASSES + c];
        o[c] = s;
    }
    #pragma unroll
    for (int c = N_CLASSES; c < HPAD; c++) o[c] = 0.f;

    float4* op = (float4*)(g_h2 + (size_t)i * HPAD);
    op[0] = make_float4(o[0],  o[1],  o[2],  o[3]);
    op[1] = make_float4(o[4],  o[5],  o[6],  o[7]);
    op[2] = make_float4(o[8],  o[9],  o[10], o[11]);
    op[3] = make_float4(o[12], o[13], o[14], o[15]);
}

// ---------------------------------------------------------------- final: log_softmax(agg2 + self + b2)
__global__ void final_kernel(const float* __restrict__ b2, float* __restrict__ out) {
    __shared__ float sb2[N_CLASSES];
    int tid = threadIdx.x;
    if (tid < N_CLASSES) sb2[tid] = b2[tid];
    __syncthreads();

    int i = blockIdx.x * blockDim.x + tid;
    if (i >= N_NODES) return;

    float dii = g_dinv[i];
    float sl  = dii * dii;

    float v[N_CLASSES];
    float mx = -INFINITY;
    #pragma unroll
    for (int c = 0; c < N_CLASSES; c++) {
        float t = g_agg2[(size_t)i * HPAD + c] + g_h2[(size_t)i * HPAD + c] * sl + sb2[c];
        v[c] = t;
        mx = fmaxf(mx, t);
    }
    float s = 0.f;
    #pragma unroll
    for (int c = 0; c < N_CLASSES; c++) s += expf(v[c] - mx);
    float ls = mx + logf(s);
    #pragma unroll
    for (int c = 0; c < N_CLASSES; c++) out[(size_t)i * N_CLASSES + c] = v[c] - ls;
}

// ---------------------------------------------------------------- launch
extern "C" void kernel_launch(void* const* d_in, const int* in_sizes, int n_in,
                              void* d_out, int out_size) {
    // Size-based input remap (robust to any metadata ordering).
    const float *W1 = 0, *b1 = 0, *W2 = 0, *b2 = 0;
    const void *big_a = 0, *big_b = 0;
    for (int i = 0; i < n_in; i++) {
        switch (in_sizes[i]) {
            case F_IN * F_HID:        W1 = (const float*)d_in[i]; break; // 2048
            case F_HID:               b1 = (const float*)d_in[i]; break; // 16
            case F_HID * N_CLASSES:   W2 = (const float*)d_in[i]; break; // 160
            case N_CLASSES:           b2 = (const float*)d_in[i]; break; // 10
            default: // the two 12.8M buffers (x and edge_index)
                if (!big_a) big_a = d_in[i]; else big_b = d_in[i];
        }
    }
    float* out = (float*)d_out;

    const int T = 256;

    probe_kernel<<<1, 32>>>(big_a, big_b);
    zero_kernel<<<(N_NODES * F_HID + T - 1) / T, T>>>();
    degree_kernel<<<(N_EDGES + T - 1) / T, T>>>();
    dinv_kernel<<<(N_NODES + T - 1) / T, T>>>();
    norm_kernel<<<(N_EDGES + T - 1) / T, T>>>();
    gemm1_kernel<<<(N_NODES + 127) / 128, 128>>>(W1);

    scatter_kernel<1><<<(N_EDGES * 4 + T - 1) / T, T>>>();
    mid_kernel<<<(N_NODES + T - 1) / T, T>>>(b1, W2);
    scatter_kernel<2><<<(N_EDGES * 4 + T - 1) / T, T>>>();
    final_kernel<<<(N_NODES + T - 1) / T, T>>>(b2, out);
}

// round 6
// speedup vs baseline: 1.3897x; 1.3897x over previous
#include <cuda_runtime.h>
#include <math.h>

#define N_NODES   100000
#define N_EDGES   6400000
#define F_IN      128
#define F_HID     16
#define N_CLASSES 10
#define HPAD      16   // layer-2 rows padded 10 -> 16 floats (64B rows)
#define SCAN_B    1024
#define SCAN_G    ((N_NODES + SCAN_B - 1) / SCAN_B)   // 98

// ---- scratch (device globals; referenced ONLY from device code) ----
__device__ int   g_deg [N_NODES];
__device__ int   g_off [N_NODES];     // CSR row start (exclusive prefix of deg)
__device__ int   g_cur [N_NODES];     // placement cursor
__device__ int   g_bsum[SCAN_G];
__device__ float g_dinv[N_NODES];
__device__ int   g_csrc[N_EDGES];     // src ids grouped by dst
__device__ __align__(16) float g_h1[N_NODES * F_HID]; // (x@W1)*dinv
__device__ __align__(16) float g_z [N_NODES * F_HID]; // relu(dinv*agg1 + b1)
__device__ __align__(16) float g_h2[N_NODES * HPAD];  // (z@W2)*dinv, padded
__device__ __align__(16) float g_a2[N_NODES * HPAD];  // dinv*agg2 (pre-bias)

// pointers resolved on-device (x vs edge_index have identical element counts)
__device__ const float* g_xp;
__device__ const int*   g_eip;

// ---------------------------------------------------------------- probe
__global__ void probe_kernel(const void* a, const void* b) {
    if (threadIdx.x != 0 || blockIdx.x != 0) return;
    const unsigned* ua = (const unsigned*)a;
    bool a_is_int = true;
    for (int i = 0; i < 16; i++)
        if (ua[i] >= 100000u) { a_is_int = false; break; }
    if (a_is_int) { g_eip = (const int*)a; g_xp = (const float*)b; }
    else          { g_eip = (const int*)b; g_xp = (const float*)a; }
}

// ---------------------------------------------------------------- zero degree
__global__ void zero_deg_kernel() {
    int i = blockIdx.x * blockDim.x + threadIdx.x;
    if (i < N_NODES) g_deg[i] = 0;
}

// ---------------------------------------------------------------- degree (over dst)
__global__ void degree_kernel() {
    int e = blockIdx.x * blockDim.x + threadIdx.x;
    const int* dst = g_eip + N_EDGES;
    if (e < N_EDGES) atomicAdd(&g_deg[dst[e]], 1);
}

// ---------------------------------------------------------------- dinv
__global__ void dinv_kernel() {
    int i = blockIdx.x * blockDim.x + threadIdx.x;
    if (i < N_NODES) g_dinv[i] = rsqrtf((float)(g_deg[i] + 1)); // +1 self-loop
}

// ---------------------------------------------------------------- scan A: per-block exclusive scan of deg
__global__ void scanA_kernel() {
    __shared__ int swarp[32];
    int i = blockIdx.x * SCAN_B + threadIdx.x;
    int lane = threadIdx.x & 31, wid = threadIdx.x >> 5;
    int v = (i < N_NODES) ? g_deg[i] : 0;
    int x = v;
    #pragma unroll
    for (int o = 1; o < 32; o <<= 1) {
        int t = __shfl_up_sync(0xffffffffu, x, o);
        if (lane >= o) x += t;
    }
    if (lane == 31) swarp[wid] = x;
    __syncthreads();
    if (wid == 0) {
        int y = swarp[lane];
        #pragma unroll
        for (int o = 1; o < 32; o <<= 1) {
            int t = __shfl_up_sync(0xffffffffu, y, o);
            if (lane >= o) y += t;
        }
        swarp[lane] = y;
    }
    __syncthreads();
    int excl = x - v + (wid > 0 ? swarp[wid - 1] : 0);
    if (i < N_NODES) g_off[i] = excl;
    if (threadIdx.x == SCAN_B - 1) g_bsum[blockIdx.x] = excl + v;
}

// ---------------------------------------------------------------- scan B: exclusive scan of block sums (SCAN_G <= 128)
__global__ void scanB_kernel() {
    __shared__ int s[128];
    int t = threadIdx.x;
    s[t] = (t < SCAN_G) ? g_bsum[t] : 0;
    __syncthreads();
    // Hillis-Steele inclusive, then shift
    for (int o = 1; o < 128; o <<= 1) {
        int v = (t >= o) ? s[t - o] : 0;
        __syncthreads();
        s[t] += v;
        __syncthreads();
    }
    if (t < SCAN_G) g_bsum[t] = (t > 0) ? s[t - 1] : 0;
}

// ---------------------------------------------------------------- scan C: add block offsets, init cursor
__global__ void scanC_kernel() {
    int i = blockIdx.x * SCAN_B + threadIdx.x;
    if (i < N_NODES) {
        int o = g_off[i] + g_bsum[blockIdx.x];
        g_off[i] = o;
        g_cur[i] = o;
    }
}

// ---------------------------------------------------------------- placement: build CSR src list
__global__ void place_kernel() {
    int e = blockIdx.x * blockDim.x + threadIdx.x;
    if (e >= N_EDGES) return;
    const int* src = g_eip;
    const int* dst = g_eip + N_EDGES;
    int d = dst[e];
    int p = atomicAdd(&g_cur[d], 1);
    g_csrc[p] = src[e];
}

// ---------------------------------------------------------------- h1s = (x @ W1) * dinv[row]
__global__ void gemm1_kernel(const float* __restrict__ W1) {
    __shared__ float sW[F_IN * F_HID];
    int tid = threadIdx.x;
    #pragma unroll
    for (int j = 0; j < 16; j++) sW[tid * 16 + j] = W1[tid * 16 + j];
    __syncthreads();

    int row = blockIdx.x * 128 + tid;
    if (row >= N_NODES) return;

    const float4* xr = (const float4*)(g_xp + (size_t)row * F_IN);
    float acc[F_HID];
    #pragma unroll
    for (int f = 0; f < F_HID; f++) acc[f] = 0.f;

    #pragma unroll 4
    for (int k4 = 0; k4 < F_IN / 4; k4++) {
        float4 xv = xr[k4];
        const float* wk = &sW[k4 * 4 * F_HID];
        #pragma unroll
        for (int f = 0; f < F_HID; f++)
            acc[f] += xv.x * wk[f] + xv.y * wk[F_HID + f]
                    + xv.z * wk[2 * F_HID + f] + xv.w * wk[3 * F_HID + f];
    }

    float di = g_dinv[row];
    float4* o = (float4*)(g_h1 + (size_t)row * F_HID);
    o[0] = make_float4(acc[0] * di,  acc[1] * di,  acc[2] * di,  acc[3] * di);
    o[1] = make_float4(acc[4] * di,  acc[5] * di,  acc[6] * di,  acc[7] * di);
    o[2] = make_float4(acc[8] * di,  acc[9] * di,  acc[10] * di, acc[11] * di);
    o[3] = make_float4(acc[12] * di, acc[13] * di, acc[14] * di, acc[15] * di);
}

// ---------------------------------------------------------------- aggregate (warp per node, no atomics)
// lane = 8 edge-slots x 4 feature-quads. acc in regs, shfl_xor reduce, one 64B store.
// LAYER 1: writes g_z = relu(dinv*A + b1).  LAYER 2: writes g_a2 = dinv*A.
template<int LAYER>
__global__ void aggregate_kernel(const float* __restrict__ bias) {
    int node = blockIdx.x * 8 + (threadIdx.x >> 5);
    if (node >= N_NODES) return;
    int lane = threadIdx.x & 31;
    int q  = lane & 3;          // feature quad
    int ei = lane >> 2;         // edge slot 0..7

    const float* h = (LAYER == 1) ? g_h1 : g_h2;
    int beg = g_off[node];
    int deg = g_deg[node];

    float4 acc = make_float4(0.f, 0.f, 0.f, 0.f);
    if (ei == 0) acc = ((const float4*)(h + (size_t)node * 16))[q];  // self-loop term

    int j = ei;
    for (; j + 8 < deg; j += 16) {
        int s0 = g_csrc[beg + j];
        int s1 = g_csrc[beg + j + 8];
        float4 v0 = ((const float4*)(h + (size_t)s0 * 16))[q];
        float4 v1 = ((const float4*)(h + (size_t)s1 * 16))[q];
        acc.x += v0.x + v1.x; acc.y += v0.y + v1.y;
        acc.z += v0.z + v1.z; acc.w += v0.w + v1.w;
    }
    if (j < deg) {
        int s0 = g_csrc[beg + j];
        float4 v0 = ((const float4*)(h + (size_t)s0 * 16))[q];
        acc.x += v0.x; acc.y += v0.y; acc.z += v0.z; acc.w += v0.w;
    }

    // reduce across edge slots (lanes differing in bits 2..4)
    #pragma unroll
    for (int m = 4; m <= 16; m <<= 1) {
        acc.x += __shfl_xor_sync(0xffffffffu, acc.x, m);
        acc.y += __shfl_xor_sync(0xffffffffu, acc.y, m);
        acc.z += __shfl_xor_sync(0xffffffffu, acc.z, m);
        acc.w += __shfl_xor_sync(0xffffffffu, acc.w, m);
    }

    if (ei == 0) {
        float di = g_dinv[node];
        float4 r;
        if (LAYER == 1) {
            float4 b = ((const float4*)bias)[q];
            r.x = fmaxf(di * acc.x + b.x, 0.f);
            r.y = fmaxf(di * acc.y + b.y, 0.f);
            r.z = fmaxf(di * acc.z + b.z, 0.f);
            r.w = fmaxf(di * acc.w + b.w, 0.f);
            ((float4*)(g_z + (size_t)node * 16))[q] = r;
        } else {
            r.x = di * acc.x; r.y = di * acc.y;
            r.z = di * acc.z; r.w = di * acc.w;
            ((float4*)(g_a2 + (size_t)node * 16))[q] = r;
        }
    }
}

// ---------------------------------------------------------------- mid: h2s = (z @ W2) * dinv (padded to 16)
__global__ void mid_kernel(const float* __restrict__ W2) {
    __shared__ float sW2[F_HID * N_CLASSES]; // 160
    int tid = threadIdx.x;
    if (tid < F_HID * N_CLASSES) sW2[tid] = W2[tid];
    __syncthreads();

    int i = blockIdx.x * blockDim.x + tid;
    if (i >= N_NODES) return;

    float z[F_HID];
    const float4* zp = (const float4*)(g_z + (size_t)i * F_HID);
    #pragma unroll
    for (int k = 0; k < 4; k++) {
        float4 v = zp[k];
        z[k * 4 + 0] = v.x; z[k * 4 + 1] = v.y; z[k * 4 + 2] = v.z; z[k * 4 + 3] = v.w;
    }

    float di = g_dinv[i];
    float o[HPAD];
    #pragma unroll
    for (int c = 0; c < N_CLASSES; c++) {
        float s = 0.f;
        #pragma unroll
        for (int f = 0; f < F_HID; f++) s += z[f] * sW2[f * N_CLASSES + c];
        o[c] = s * di;
    }
    #pragma unroll
    for (int c = N_CLASSES; c < HPAD; c++) o[c] = 0.f;

    float4* op = (float4*)(g_h2 + (size_t)i * HPAD);
    op[0] = make_float4(o[0],  o[1],  o[2],  o[3]);
    op[1] = make_float4(o[4],  o[5],  o[6],  o[7]);
    op[2] = make_float4(o[8],  o[9],  o[10], o[11]);
    op[3] = make_float4(o[12], o[13], o[14], o[15]);
}

// ---------------------------------------------------------------- final: log_softmax(a2 + b2)
__global__ void final_kernel(const float* __restrict__ b2, float* __restrict__ out) {
    __shared__ float sb2[N_CLASSES];
    int tid = threadIdx.x;
    if (tid < N_CLASSES) sb2[tid] = b2[tid];
    __syncthreads();

    int i = blockIdx.x * blockDim.x + tid;
    if (i >= N_NODES) return;

    float v[N_CLASSES];
    float mx = -INFINITY;
    #pragma unroll
    for (int c = 0; c < N_CLASSES; c++) {
        float t = g_a2[(size_t)i * HPAD + c] + sb2[c];
        v[c] = t;
        mx = fmaxf(mx, t);
    }
    float s = 0.f;
    #pragma unroll
    for (int c = 0; c < N_CLASSES; c++) s += expf(v[c] - mx);
    float ls = mx + logf(s);
    #pragma unroll
    for (int c = 0; c < N_CLASSES; c++) out[(size_t)i * N_CLASSES + c] = v[c] - ls;
}

// ---------------------------------------------------------------- launch
extern "C" void kernel_launch(void* const* d_in, const int* in_sizes, int n_in,
                              void* d_out, int out_size) {
    const float *W1 = 0, *b1 = 0, *W2 = 0, *b2 = 0;
    const void *big_a = 0, *big_b = 0;
    for (int i = 0; i < n_in; i++) {
        switch (in_sizes[i]) {
            case F_IN * F_HID:      W1 = (const float*)d_in[i]; break; // 2048
            case F_HID:             b1 = (const float*)d_in[i]; break; // 16
            case F_HID * N_CLASSES: W2 = (const float*)d_in[i]; break; // 160
            case N_CLASSES:         b2 = (const float*)d_in[i]; break; // 10
            default:
                if (!big_a) big_a = d_in[i]; else big_b = d_in[i];
        }
    }
    float* out = (float*)d_out;

    const int T = 256;
    const int NODE_G = (N_NODES + T - 1) / T;
    const int EDGE_G = (N_EDGES + T - 1) / T;
    const int AGG_G  = (N_NODES + 7) / 8;   // warp per node, 8 warps/block

    probe_kernel<<<1, 32>>>(big_a, big_b);
    zero_deg_kernel<<<NODE_G, T>>>();
    degree_kernel<<<EDGE_G, T>>>();
    dinv_kernel<<<NODE_G, T>>>();
    scanA_kernel<<<SCAN_G, SCAN_B>>>();
    scanB_kernel<<<1, 128>>>();
    scanC_kernel<<<SCAN_G, SCAN_B>>>();
    place_kernel<<<EDGE_G, T>>>();
    gemm1_kernel<<<(N_NODES + 127) / 128, 128>>>(W1);

    aggregate_kernel<1><<<AGG_G, T>>>(b1);
    mid_kernel<<<NODE_G, T>>>(W2);
    aggregate_kernel<2><<<AGG_G, T>>>(b2 /*unused*/);
    final_kernel<<<NODE_G, T>>>(b2, out);
}

// round 7
// speedup vs baseline: 1.4287x; 1.0281x over previous
#include <cuda_runtime.h>
#include <cuda_bf16.h>
#include <math.h>

#define N_NODES   100000
#define N_EDGES   6400000
#define F_IN      128
#define F_HID     16
#define N_CLASSES 10
#define HPAD      16
#define SCAN_B    1024
#define SCAN_G    ((N_NODES + SCAN_B - 1) / SCAN_B)   // 98

// ---- scratch (device globals; referenced ONLY from device code) ----
__device__ int   g_deg [N_NODES];
__device__ int   g_off [N_NODES];
__device__ int   g_cur [N_NODES];
__device__ int   g_bsum[SCAN_G];
__device__ float g_dinv[N_NODES];
__device__ int   g_csrc[N_EDGES];                        // src ids grouped by dst
__device__ __align__(32) __nv_bfloat16 g_h1b[N_NODES * 16]; // (x@W1)*dinv, bf16
__device__ __align__(32) __nv_bfloat16 g_h2b[N_NODES * 16]; // (z@W2)*dinv, bf16 (10+pad)
__device__ __align__(16) float g_z[N_NODES * F_HID];     // relu(dinv*agg1 + b1), fp32

__device__ const float* g_xp;
__device__ const int*   g_eip;

// ---------------------------------------------------------------- probe + zero deg
__global__ void probe_zero_kernel(const void* a, const void* b) {
    int i = blockIdx.x * blockDim.x + threadIdx.x;
    if (i == 0) {
        const unsigned* ua = (const unsigned*)a;
        bool a_is_int = true;
        for (int k = 0; k < 16; k++)
            if (ua[k] >= 100000u) { a_is_int = false; break; }
        if (a_is_int) { g_eip = (const int*)a; g_xp = (const float*)b; }
        else          { g_eip = (const int*)b; g_xp = (const float*)a; }
    }
    if (i < N_NODES) g_deg[i] = 0;
}

// ---------------------------------------------------------------- degree (over dst)
__global__ void degree_kernel() {
    int e = blockIdx.x * blockDim.x + threadIdx.x;
    const int* dst = g_eip + N_EDGES;
    if (e < N_EDGES) atomicAdd(&g_deg[dst[e]], 1);
}

// ---------------------------------------------------------------- scan A (+ dinv fused)
__global__ void scanA_kernel() {
    __shared__ int swarp[32];
    int i = blockIdx.x * SCAN_B + threadIdx.x;
    int lane = threadIdx.x & 31, wid = threadIdx.x >> 5;
    int v = (i < N_NODES) ? g_deg[i] : 0;
    if (i < N_NODES) g_dinv[i] = rsqrtf((float)(v + 1));  // fused dinv (+1 self-loop)
    int x = v;
    #pragma unroll
    for (int o = 1; o < 32; o <<= 1) {
        int t = __shfl_up_sync(0xffffffffu, x, o);
        if (lane >= o) x += t;
    }
    if (lane == 31) swarp[wid] = x;
    __syncthreads();
    if (wid == 0) {
        int y = swarp[lane];
        #pragma unroll
        for (int o = 1; o < 32; o <<= 1) {
            int t = __shfl_up_sync(0xffffffffu, y, o);
            if (lane >= o) y += t;
        }
        swarp[lane] = y;
    }
    __syncthreads();
    int excl = x - v + (wid > 0 ? swarp[wid - 1] : 0);
    if (i < N_NODES) g_off[i] = excl;
    if (threadIdx.x == SCAN_B - 1) g_bsum[blockIdx.x] = excl + v;
}

// ---------------------------------------------------------------- scan B
__global__ void scanB_kernel() {
    __shared__ int s[128];
    int t = threadIdx.x;
    s[t] = (t < SCAN_G) ? g_bsum[t] : 0;
    __syncthreads();
    for (int o = 1; o < 128; o <<= 1) {
        int v = (t >= o) ? s[t - o] : 0;
        __syncthreads();
        s[t] += v;
        __syncthreads();
    }
    if (t < SCAN_G) g_bsum[t] = (t > 0) ? s[t - 1] : 0;
}

// ---------------------------------------------------------------- scan C
__global__ void scanC_kernel() {
    int i = blockIdx.x * SCAN_B + threadIdx.x;
    if (i < N_NODES) {
        int o = g_off[i] + g_bsum[blockIdx.x];
        g_off[i] = o;
        g_cur[i] = o;
    }
}

// ---------------------------------------------------------------- placement: CSR src list
__global__ void place_kernel() {
    int e = blockIdx.x * blockDim.x + threadIdx.x;
    if (e >= N_EDGES) return;
    const int* src = g_eip;
    const int* dst = g_eip + N_EDGES;
    int d = dst[e];
    int p = atomicAdd(&g_cur[d], 1);
    g_csrc[p] = src[e];
}

// ---------------------------------------------------------------- h1b = bf16((x @ W1) * dinv)
__global__ void gemm1_kernel(const float* __restrict__ W1) {
    __shared__ float sW[F_IN * F_HID];
    int tid = threadIdx.x;
    #pragma unroll
    for (int j = 0; j < 16; j++) sW[tid * 16 + j] = W1[tid * 16 + j];
    __syncthreads();

    int row = blockIdx.x * 128 + tid;
    if (row >= N_NODES) return;

    const float4* xr = (const float4*)(g_xp + (size_t)row * F_IN);
    float acc[F_HID];
    #pragma unroll
    for (int f = 0; f < F_HID; f++) acc[f] = 0.f;

    #pragma unroll 4
    for (int k4 = 0; k4 < F_IN / 4; k4++) {
        float4 xv = xr[k4];
        const float* wk = &sW[k4 * 4 * F_HID];
        #pragma unroll
        for (int f = 0; f < F_HID; f++)
            acc[f] += xv.x * wk[f] + xv.y * wk[F_HID + f]
                    + xv.z * wk[2 * F_HID + f] + xv.w * wk[3 * F_HID + f];
    }

    float di = g_dinv[row];
    unsigned w[8];
    #pragma unroll
    for (int k = 0; k < 8; k++) {
        __nv_bfloat162 p = __floats2bfloat162_rn(acc[2 * k] * di, acc[2 * k + 1] * di);
        w[k] = *(unsigned*)&p;
    }
    uint4* o = (uint4*)(g_h1b + (size_t)row * 16);
    o[0] = make_uint4(w[0], w[1], w[2], w[3]);
    o[1] = make_uint4(w[4], w[5], w[6], w[7]);
}

// ---------------------------------------------------------------- aggregate (warp/node, bf16 gather, fp32 accum)
// lane: q = lane&3 (8B chunk = 4 bf16), ei = lane>>2 (8 edge slots).
// LAYER 1: z = relu(dinv*A + b1) fp32.  LAYER 2: fused log_softmax -> out.
template<int LAYER>
__global__ void aggregate_kernel(const float* __restrict__ bias, float* __restrict__ out) {
    int node = blockIdx.x * 8 + (threadIdx.x >> 5);
    if (node >= N_NODES) return;
    int lane = threadIdx.x & 31;
    int q  = lane & 3;
    int ei = lane >> 2;

    const __nv_bfloat16* hb = (LAYER == 1) ? g_h1b : g_h2b;
    int beg = g_off[node];
    int deg = g_deg[node];

    float a0 = 0.f, a1 = 0.f, a2 = 0.f, a3 = 0.f;
    if (ei == 0) {
        uint2 raw = *(const uint2*)(hb + (size_t)node * 16 + q * 4);
        float2 f0 = __bfloat1622float2(*(__nv_bfloat162*)&raw.x);
        float2 f1 = __bfloat1622float2(*(__nv_bfloat162*)&raw.y);
        a0 = f0.x; a1 = f0.y; a2 = f1.x; a3 = f1.y;   // self-loop term
    }

    int j = ei;
    for (; j + 8 < deg; j += 16) {
        int s0 = g_csrc[beg + j];
        int s1 = g_csrc[beg + j + 8];
        uint2 r0 = *(const uint2*)(hb + (size_t)s0 * 16 + q * 4);
        uint2 r1 = *(const uint2*)(hb + (size_t)s1 * 16 + q * 4);
        float2 x0 = __bfloat1622float2(*(__nv_bfloat162*)&r0.x);
        float2 x1 = __bfloat1622float2(*(__nv_bfloat162*)&r0.y);
        float2 y0 = __bfloat1622float2(*(__nv_bfloat162*)&r1.x);
        float2 y1 = __bfloat1622float2(*(__nv_bfloat162*)&r1.y);
        a0 += x0.x + y0.x; a1 += x0.y + y0.y;
        a2 += x1.x + y1.x; a3 += x1.y + y1.y;
    }
    if (j < deg) {
        int s0 = g_csrc[beg + j];
        uint2 r0 = *(const uint2*)(hb + (size_t)s0 * 16 + q * 4);
        float2 x0 = __bfloat1622float2(*(__nv_bfloat162*)&r0.x);
        float2 x1 = __bfloat1622float2(*(__nv_bfloat162*)&r0.y);
        a0 += x0.x; a1 += x0.y; a2 += x1.x; a3 += x1.y;
    }

    // reduce across edge slots (lane bits 2..4); afterwards ALL lanes hold full sums
    #pragma unroll
    for (int m = 4; m <= 16; m <<= 1) {
        a0 += __shfl_xor_sync(0xffffffffu, a0, m);
        a1 += __shfl_xor_sync(0xffffffffu, a1, m);
        a2 += __shfl_xor_sync(0xffffffffu, a2, m);
        a3 += __shfl_xor_sync(0xffffffffu, a3, m);
    }

    float di = g_dinv[node];

    if (LAYER == 1) {
        if (ei == 0) {
            float4 b = ((const float4*)bias)[q];
            float4 r;
            r.x = fmaxf(di * a0 + b.x, 0.f);
            r.y = fmaxf(di * a1 + b.y, 0.f);
            r.z = fmaxf(di * a2 + b.z, 0.f);
            r.w = fmaxf(di * a3 + b.w, 0.f);
            ((float4*)(g_z + (size_t)node * 16))[q] = r;
        }
    } else {
        // fused log_softmax over classes 0..9 (lane q holds classes 4q..4q+3)
        float l[4];
        l[0] = di * a0; l[1] = di * a1; l[2] = di * a2; l[3] = di * a3;
        int base = q * 4;
        float mx = -1e30f;
        #pragma unroll
        for (int k = 0; k < 4; k++) {
            if (base + k < N_CLASSES) { l[k] += bias[base + k]; mx = fmaxf(mx, l[k]); }
        }
        mx = fmaxf(mx, __shfl_xor_sync(0xffffffffu, mx, 1));
        mx = fmaxf(mx, __shfl_xor_sync(0xffffffffu, mx, 2));
        float se = 0.f;
        #pragma unroll
        for (int k = 0; k < 4; k++)
            if (base + k < N_CLASSES) se += expf(l[k] - mx);
        se += __shfl_xor_sync(0xffffffffu, se, 1);
        se += __shfl_xor_sync(0xffffffffu, se, 2);
        float ls = mx + logf(se);
        if (ei == 0) {
            float* op = out + (size_t)node * N_CLASSES + base;
            if (q < 2) {  // classes 0-7: two 8B stores each
                *(float2*)(op)     = make_float2(l[0] - ls, l[1] - ls);
                *(float2*)(op + 2) = make_float2(l[2] - ls, l[3] - ls);
            } else if (q == 2) {  // classes 8,9
                *(float2*)(op) = make_float2(l[0] - ls, l[1] - ls);
            }
        }
    }
}

// ---------------------------------------------------------------- mid: h2b = bf16((z @ W2) * dinv), padded
__global__ void mid_kernel(const float* __restrict__ W2) {
    __shared__ float sW2[F_HID * N_CLASSES];
    int tid = threadIdx.x;
    if (tid < F_HID * N_CLASSES) sW2[tid] = W2[tid];
    __syncthreads();

    int i = blockIdx.x * blockDim.x + tid;
    if (i >= N_NODES) return;

    float z[F_HID];
    const float4* zp = (const float4*)(g_z + (size_t)i * F_HID);
    #pragma unroll
    for (int k = 0; k < 4; k++) {
        float4 v = zp[k];
        z[k * 4 + 0] = v.x; z[k * 4 + 1] = v.y; z[k * 4 + 2] = v.z; z[k * 4 + 3] = v.w;
    }

    float di = g_dinv[i];
    float o[HPAD];
    #pragma unroll
    for (int c = 0; c < N_CLASSES; c++) {
        float s = 0.f;
        #pragma unroll
        for (int f = 0; f < F_HID; f++) s += z[f] * sW2[f * N_CLASSES + c];
        o[c] = s * di;
    }
    #pragma unroll
    for (int c = N_CLASSES; c < HPAD; c++) o[c] = 0.f;

    unsigned w[8];
    #pragma unroll
    for (int k = 0; k < 8; k++) {
        __nv_bfloat162 p = __floats2bfloat162_rn(o[2 * k], o[2 * k + 1]);
        w[k] = *(unsigned*)&p;
    }
    uint4* op = (uint4*)(g_h2b + (size_t)i * 16);
    op[0] = make_uint4(w[0], w[1], w[2], w[3]);
    op[1] = make_uint4(w[4], w[5], w[6], w[7]);
}

// ---------------------------------------------------------------- launch
extern "C" void kernel_launch(void* const* d_in, const int* in_sizes, int n_in,
                              void* d_out, int out_size) {
    const float *W1 = 0, *b1 = 0, *W2 = 0, *b2 = 0;
    const void *big_a = 0, *big_b = 0;
    for (int i = 0; i < n_in; i++) {
        switch (in_sizes[i]) {
            case F_IN * F_HID:      W1 = (const float*)d_in[i]; break;
            case F_HID:             b1 = (const float*)d_in[i]; break;
            case F_HID * N_CLASSES: W2 = (const float*)d_in[i]; break;
            case N_CLASSES:         b2 = (const float*)d_in[i]; break;
            default:
                if (!big_a) big_a = d_in[i]; else big_b = d_in[i];
        }
    }
    float* out = (float*)d_out;

    const int T = 256;
    const int NODE_G = (N_NODES + T - 1) / T;
    const int EDGE_G = (N_EDGES + T - 1) / T;
    const int AGG_G  = (N_NODES + 7) / 8;

    probe_zero_kernel<<<NODE_G, T>>>(big_a, big_b);
    degree_kernel<<<EDGE_G, T>>>();
    scanA_kernel<<<SCAN_G, SCAN_B>>>();
    scanB_kernel<<<1, 128>>>();
    scanC_kernel<<<SCAN_G, SCAN_B>>>();
    place_kernel<<<EDGE_G, T>>>();
    gemm1_kernel<<<(N_NODES + 127) / 128, 128>>>(W1);

    aggregate_kernel<1><<<AGG_G, T>>>(b1, nullptr);
    mid_kernel<<<NODE_G, T>>>(W2);
    aggregate_kernel<2><<<AGG_G, T>>>(b2, out);
}